// round 4
// baseline (speedup 1.0000x reference)
#include <cuda_runtime.h>
#include <cuda_bf16.h>
#include <math.h>
#include <stdint.h>

#define T_STEPS 128
#define B_ENV   128
#define HID     512
#define TBTOT   (T_STEPS * B_ENV)
#define ZD      8
#define AD      7
#define FE      128

typedef unsigned long long ull;

// ----------------------------------------------------------------------------
// Scratch (device globals; no allocation allowed)
// ----------------------------------------------------------------------------
__device__ float g_conv[TBTOT * 4096];
__device__ float g_h1[TBTOT * HID];
__device__ float g_h2[TBTOT * HID];
__device__ float g_xg[TBTOT * 2048];
__device__ float g_feat[TBTOT * HID];
__device__ float g_lf[TBTOT * FE];
__device__ float g_hA[B_ENV * HID];
__device__ float g_hB[B_ENV * HID];
__device__ float g_c[B_ENV * HID];
__device__ __nv_bfloat16 g_wfc1_hi[512 * 4096];
__device__ __nv_bfloat16 g_wfc1_lo[512 * 4096];
__device__ __nv_bfloat16 g_wfc2_hi[512 * 512];
__device__ __nv_bfloat16 g_wfc2_lo[512 * 512];
__device__ __nv_bfloat16 g_wih_hi[2048 * 512];
__device__ __nv_bfloat16 g_wih_lo[2048 * 512];

// ============================================================================
// Helpers
// ============================================================================
__device__ __forceinline__ uint32_t smem_to_u32(const void* smem_ptr) {
    uint32_t addr;
    asm("{ .reg .u64 tmp; cvta.to.shared.u64 tmp, %1; cvt.u32.u64 %0, tmp; }"
        : "=r"(addr) : "l"(smem_ptr));
    return addr;
}

__device__ __forceinline__ void ldsm4(uint32_t addr, uint32_t* r) {
    asm volatile("ldmatrix.sync.aligned.m8n8.x4.shared.b16 {%0,%1,%2,%3}, [%4];"
        : "=r"(r[0]), "=r"(r[1]), "=r"(r[2]), "=r"(r[3]) : "r"(addr));
}

__device__ __forceinline__ void mma16816(float* d, const uint32_t* a,
                                         const uint32_t* b) {
    asm volatile(
        "mma.sync.aligned.m16n8k16.row.col.f32.bf16.bf16.f32 "
        "{%0,%1,%2,%3}, {%4,%5,%6,%7}, {%8,%9}, {%0,%1,%2,%3};"
        : "+f"(d[0]), "+f"(d[1]), "+f"(d[2]), "+f"(d[3])
        : "r"(a[0]), "r"(a[1]), "r"(a[2]), "r"(a[3]), "r"(b[0]), "r"(b[1]));
}

// packed fp32x2 FMA (Blackwell base-family PTX)
__device__ __forceinline__ void ffma2(ull& d, ull a, ull b) {
    asm("fma.rn.f32x2 %0, %1, %2, %0;" : "+l"(d) : "l"(a), "l"(b));
}
__device__ __forceinline__ ull fpack(float x, float y) {
    ull r;
    asm("mov.b64 %0, {%1, %2};" : "=l"(r) : "f"(x), "f"(y));
    return r;
}
__device__ __forceinline__ void funpack(ull a, float& x, float& y) {
    asm("mov.b64 {%0, %1}, %2;" : "=f"(x), "=f"(y) : "l"(a));
}

__device__ __forceinline__ void split2(float x, float y, uint32_t& hi, uint32_t& lo) {
    __nv_bfloat16 hx = __float2bfloat16(x), hy = __float2bfloat16(y);
    __nv_bfloat162 h2; h2.x = hx; h2.y = hy;
    hi = reinterpret_cast<uint32_t&>(h2);
    float lx = x - __bfloat162float(hx);
    float ly = y - __bfloat162float(hy);
    __nv_bfloat162 l2 = __floats2bfloat162_rn(lx, ly);
    lo = reinterpret_cast<uint32_t&>(l2);
}

// ----------------------------------------------------------------------------
// Weight prep: fp32 [N,K] row-major -> bf16 hi/lo row-major
// ----------------------------------------------------------------------------
__global__ void wprep(const float* __restrict__ w, __nv_bfloat16* __restrict__ hi,
                      __nv_bfloat16* __restrict__ lo, int total4) {
    int idx = blockIdx.x * blockDim.x + threadIdx.x;
    if (idx >= total4) return;
    float4 a = *(const float4*)(w + (size_t)idx * 4);
    uint32_t h0, h1, l0, l1;
    split2(a.x, a.y, h0, l0);
    split2(a.z, a.w, h1, l1);
    *(uint2*)(hi + (size_t)idx * 4) = make_uint2(h0, h1);
    *(uint2*)(lo + (size_t)idx * 4) = make_uint2(l0, l1);
}

// ----------------------------------------------------------------------------
// HMMA GEMM (unchanged from R3): 3-term bf16 split, fp32 accum
// ----------------------------------------------------------------------------
#define SMSTR 80

template <int ACT>
__global__ __launch_bounds__(256) void tgemm(
    const float* __restrict__ A, const __nv_bfloat16* __restrict__ Whi,
    const __nv_bfloat16* __restrict__ Wlo,
    const float* __restrict__ bias, const float* __restrict__ bias2,
    float* __restrict__ C, int M, int N, int K) {
    extern __shared__ uint8_t sm[];
    const uint32_t oAh = 0, oAl = 10240, oBh = 20480, oBl = 30720;
    uint32_t sb = smem_to_u32(sm);
    int tid = threadIdx.x;
    int lane = tid & 31;
    int wid = tid >> 5;
    int wm = wid & 3, wn = wid >> 2;
    int m0 = blockIdx.y * 128, n0 = blockIdx.x * 128;
    const float* Ag = A + (size_t)m0 * K;

    float acc[2][8][4];
#pragma unroll
    for (int i = 0; i < 2; i++)
#pragma unroll
        for (int j = 0; j < 8; j++)
#pragma unroll
            for (int q = 0; q < 4; q++) acc[i][j][q] = 0.f;

    int nslab = K / 32;
    float4 aR[4];
    uint4 bRh[2], bRl[2];

    auto load_slab = [&](int s) {
#pragma unroll
        for (int i = 0; i < 4; i++) {
            int row = (tid >> 3) + 32 * i;
            aR[i] = *(const float4*)(Ag + (size_t)row * K + s * 32 + (tid & 7) * 4);
        }
#pragma unroll
        for (int i = 0; i < 2; i++) {
            int row = (tid >> 2) + 64 * i;
            size_t boff = ((size_t)(n0 + row) * K + s * 32);
            bRh[i] = *(const uint4*)((const uint8_t*)(Whi + boff) + (tid & 3) * 16);
            bRl[i] = *(const uint4*)((const uint8_t*)(Wlo + boff) + (tid & 3) * 16);
        }
    };
    auto store_slab = [&]() {
#pragma unroll
        for (int i = 0; i < 4; i++) {
            int row = (tid >> 3) + 32 * i;
            int col8 = (tid & 7) * 8;
            uint32_t h0, h1, l0, l1;
            split2(aR[i].x, aR[i].y, h0, l0);
            split2(aR[i].z, aR[i].w, h1, l1);
            *(uint2*)(sm + oAh + row * SMSTR + col8) = make_uint2(h0, h1);
            *(uint2*)(sm + oAl + row * SMSTR + col8) = make_uint2(l0, l1);
        }
#pragma unroll
        for (int i = 0; i < 2; i++) {
            int row = (tid >> 2) + 64 * i;
            int c16 = (tid & 3) * 16;
            *(uint4*)(sm + oBh + row * SMSTR + c16) = bRh[i];
            *(uint4*)(sm + oBl + row * SMSTR + c16) = bRl[i];
        }
    };

    load_slab(0);
    store_slab();
    __syncthreads();

    int g = lane >> 3;
    int arow_off = (lane & 7) + (g & 1) * 8;
    int akb_off = (g >> 1) * 16;
    int brow_off = (lane & 7) + (g >> 1) * 8;
    int bkb_off = (g & 1) * 16;

    for (int s = 0; s < nslab; s++) {
        bool more = (s + 1 < nslab);
        if (more) load_slab(s + 1);

#pragma unroll
        for (int kk2 = 0; kk2 < 2; kk2++) {
            int kb = kk2 * 32;
            uint32_t ah[2][4], al[2][4], bh[4][4], bl[4][4];
#pragma unroll
            for (int mi = 0; mi < 2; mi++) {
                uint32_t r = (uint32_t)((wm * 32 + mi * 16 + arow_off) * SMSTR +
                                        kb + akb_off);
                ldsm4(sb + oAh + r, ah[mi]);
                ldsm4(sb + oAl + r, al[mi]);
            }
#pragma unroll
            for (int pi = 0; pi < 4; pi++) {
                uint32_t r = (uint32_t)((wn * 64 + pi * 16 + brow_off) * SMSTR +
                                        kb + bkb_off);
                ldsm4(sb + oBh + r, bh[pi]);
                ldsm4(sb + oBl + r, bl[pi]);
            }
#pragma unroll
            for (int mi = 0; mi < 2; mi++)
#pragma unroll
                for (int pi = 0; pi < 4; pi++)
#pragma unroll
                    for (int half = 0; half < 2; half++) {
                        float* d = acc[mi][pi * 2 + half];
                        mma16816(d, ah[mi], &bh[pi][half * 2]);
                        mma16816(d, ah[mi], &bl[pi][half * 2]);
                        mma16816(d, al[mi], &bh[pi][half * 2]);
                    }
        }
        __syncthreads();
        if (more) {
            store_slab();
            __syncthreads();
        }
    }

    float* ct = (float*)sm;
#pragma unroll
    for (int mi = 0; mi < 2; mi++) {
        int r0 = wm * 32 + mi * 16 + (lane >> 2);
#pragma unroll
        for (int ni = 0; ni < 8; ni++) {
            int c = wn * 64 + ni * 8 + (lane & 3) * 2;
            float b0 = bias[n0 + c], b1 = bias[n0 + c + 1];
            if (bias2) { b0 += bias2[n0 + c]; b1 += bias2[n0 + c + 1]; }
            float v0 = acc[mi][ni][0] + b0;
            float v1 = acc[mi][ni][1] + b1;
            float v2 = acc[mi][ni][2] + b0;
            float v3 = acc[mi][ni][3] + b1;
            if (ACT) {
                v0 = v0 > 0.f ? v0 : 0.01f * v0;
                v1 = v1 > 0.f ? v1 : 0.01f * v1;
                v2 = v2 > 0.f ? v2 : 0.01f * v2;
                v3 = v3 > 0.f ? v3 : 0.01f * v3;
            }
            ct[r0 * 132 + c] = v0;
            ct[r0 * 132 + c + 1] = v1;
            ct[(r0 + 8) * 132 + c] = v2;
            ct[(r0 + 8) * 132 + c + 1] = v3;
        }
    }
    __syncthreads();
    {
        int r8 = tid >> 5;
        int c4 = (tid & 31) * 4;
#pragma unroll
        for (int p = 0; p < 16; p++) {
            int r = p * 8 + r8;
            float4 v = *(const float4*)(ct + r * 132 + c4);
            *(float4*)(C + (size_t)(m0 + r) * N + n0 + c4) = v;
        }
    }
}

// ----------------------------------------------------------------------------
// Conv v2: ci-pair packed f32x2.
// smem image: 8 ci-pairs x 20x20 float2 (zero halo), plane stride 402 ull.
// Thread map: co = tid&15 (warp-fast -> row loads broadcast), h = tid>>4.
// ----------------------------------------------------------------------------
template <int KS, int P>
__device__ __forceinline__ void conv_stage2(const ull* __restrict__ s_img,
                                            const ull* __restrict__ s_w2,
                                            float bv, int co, int h,
                                            float* out) {
    ull acc[16];
#pragma unroll
    for (int w = 0; w < 16; w++) acc[w] = 0ull;
#pragma unroll 1
    for (int cp = 0; cp < 8; cp++) {
        const ull* wbase = s_w2 + (cp * 16 + co) * (KS * KS + 1);
        const ull* plane = s_img + cp * 402;
#pragma unroll
        for (int kh = 0; kh < KS; kh++) {
            int ro = h + kh - P + 2;
            const ull* rp = plane + ro * 20;
            ull row[20];
#pragma unroll
            for (int q = 0; q < 10; q++) {
                ulonglong2 tt = *(const ulonglong2*)(rp + q * 2);
                row[2 * q] = tt.x;
                row[2 * q + 1] = tt.y;
            }
#pragma unroll
            for (int kw = 0; kw < KS; kw++) {
                ull wv = wbase[kh * KS + kw];
#pragma unroll
                for (int w = 0; w < 16; w++)
                    ffma2(acc[w], row[w + kw + 2 - P], wv);
            }
        }
    }
#pragma unroll
    for (int w = 0; w < 16; w++) {
        float lo, hi;
        funpack(acc[w], lo, hi);
        float v = lo + hi + bv;
        out[w] = v > 0.f ? v : 0.01f * v;
    }
}

__global__ __launch_bounds__(256) void conv3_v2(
    const float* __restrict__ x,
    const float* __restrict__ w1, const float* __restrict__ b1,
    const float* __restrict__ w2, const float* __restrict__ b2,
    const float* __restrict__ w3, const float* __restrict__ b3) {
    extern __shared__ ull sm8[];
    ull* s_img = sm8;               // 3216 ull
    ull* s_wp = sm8 + 3216;         // up to 3328 ull
    float* s_b = (float*)(sm8 + 3216 + 3328);

    int tid = threadIdx.x;
    int img = blockIdx.x;
    int co = tid & 15, h = tid >> 4;
    const float* xi = x + (size_t)img * 4096;

    // zero image (halo relies on this)
    for (int i = tid; i < 3216; i += 256) s_img[i] = 0ull;
    __syncthreads();
    // fill interior as ci-pairs
    for (int i = tid; i < 2048; i += 256) {
        int cp = i >> 8, r = i & 255;
        s_img[cp * 402 + ((r >> 4) + 2) * 20 + (r & 15) + 2] =
            fpack(xi[cp * 512 + r], xi[cp * 512 + 256 + r]);
    }
    // conv1 weight pairs, layout [cp][co][26]
    for (int i = tid; i < 3200; i += 256) {
        int t = i % 25, rest = i / 25;
        int coo = rest & 15, cp = rest >> 4;
        s_wp[(cp * 16 + coo) * 26 + t] =
            fpack(w1[(coo * 16 + 2 * cp) * 25 + t],
                  w1[(coo * 16 + 2 * cp + 1) * 25 + t]);
    }
    if (tid < 16) s_b[tid] = b1[tid];
    __syncthreads();

    float out[16];
    conv_stage2<5, 2>(s_img, s_wp, s_b[co], co, h, out);
    __syncthreads();
    {   // write activations back as ci-pairs (scalar component stores)
        float* simf = (float*)s_img;
        int base = (co >> 1) * 804 + (h + 2) * 40 + (co & 1);
#pragma unroll
        for (int w = 0; w < 16; w++) simf[base + (w + 2) * 2] = out[w];
    }
    for (int i = tid; i < 1152; i += 256) {
        int t = i % 9, rest = i / 9;
        int coo = rest & 15, cp = rest >> 4;
        s_wp[(cp * 16 + coo) * 10 + t] =
            fpack(w2[(coo * 16 + 2 * cp) * 9 + t],
                  w2[(coo * 16 + 2 * cp + 1) * 9 + t]);
    }
    if (tid < 16) s_b[tid] = b2[tid];
    __syncthreads();

    conv_stage2<3, 1>(s_img, s_wp, s_b[co], co, h, out);
    __syncthreads();
    {
        float* simf = (float*)s_img;
        int base = (co >> 1) * 804 + (h + 2) * 40 + (co & 1);
#pragma unroll
        for (int w = 0; w < 16; w++) simf[base + (w + 2) * 2] = out[w];
    }
    for (int i = tid; i < 1152; i += 256) {
        int t = i % 9, rest = i / 9;
        int coo = rest & 15, cp = rest >> 4;
        s_wp[(cp * 16 + coo) * 10 + t] =
            fpack(w3[(coo * 16 + 2 * cp) * 9 + t],
                  w3[(coo * 16 + 2 * cp + 1) * 9 + t]);
    }
    if (tid < 16) s_b[tid] = b3[tid];
    __syncthreads();

    conv_stage2<3, 1>(s_img, s_wp, s_b[co], co, h, out);
    float4* og = (float4*)(g_conv + (size_t)img * 4096 + co * 256 + h * 16);
#pragma unroll
    for (int q = 0; q < 4; q++)
        og[q] = make_float4(out[4 * q], out[4 * q + 1], out[4 * q + 2],
                            out[4 * q + 3]);
}

// ----------------------------------------------------------------------------
// Scalar SGEMM kept for lofeat (with z one-hot epilogue)
// ----------------------------------------------------------------------------
template <int ACT, int ZMODE>
__global__ __launch_bounds__(256, 2) void sgemm128(
    const float* __restrict__ A, const float* __restrict__ B,
    const float* __restrict__ bias, const float* __restrict__ bias2,
    float* __restrict__ C, int M, int N, int K, int ldb,
    const int* __restrict__ z) {
    __shared__ float As[8 * 132];
    __shared__ float Bs[8 * 132];
    int tid = threadIdx.x;
    int tx = tid & 15, ty = tid >> 4;
    int row0 = blockIdx.y * 128;
    int col0 = blockIdx.x * 128;
    const float* Ag = A + (size_t)row0 * K;
    const float* Bg = B + (size_t)col0 * ldb;
    int lr = tid >> 1;
    int lc = (tid & 1) * 4;

    float acc[8][8];
#pragma unroll
    for (int i = 0; i < 8; i++)
#pragma unroll
        for (int j = 0; j < 8; j++) acc[i][j] = 0.f;

    for (int k0 = 0; k0 < K; k0 += 8) {
        float4 a4 = *(const float4*)(Ag + (size_t)lr * K + k0 + lc);
        float4 b4 = *(const float4*)(Bg + (size_t)lr * ldb + k0 + lc);
        As[(lc + 0) * 132 + lr] = a4.x;
        As[(lc + 1) * 132 + lr] = a4.y;
        As[(lc + 2) * 132 + lr] = a4.z;
        As[(lc + 3) * 132 + lr] = a4.w;
        Bs[(lc + 0) * 132 + lr] = b4.x;
        Bs[(lc + 1) * 132 + lr] = b4.y;
        Bs[(lc + 2) * 132 + lr] = b4.z;
        Bs[(lc + 3) * 132 + lr] = b4.w;
        __syncthreads();
#pragma unroll
        for (int k = 0; k < 8; k++) {
            float4 a0 = *(const float4*)(As + k * 132 + ty * 4);
            float4 a1 = *(const float4*)(As + k * 132 + 64 + ty * 4);
            float4 b0 = *(const float4*)(Bs + k * 132 + tx * 4);
            float4 b1 = *(const float4*)(Bs + k * 132 + 64 + tx * 4);
            float av[8] = {a0.x, a0.y, a0.z, a0.w, a1.x, a1.y, a1.z, a1.w};
            float bv[8] = {b0.x, b0.y, b0.z, b0.w, b1.x, b1.y, b1.z, b1.w};
#pragma unroll
            for (int i = 0; i < 8; i++)
#pragma unroll
                for (int j = 0; j < 8; j++)
                    acc[i][j] = fmaf(av[i], bv[j], acc[i][j]);
        }
        __syncthreads();
    }

#pragma unroll
    for (int i = 0; i < 8; i++) {
        int m = row0 + ((i < 4) ? (ty * 4 + i) : (64 + ty * 4 + i - 4));
        int zi = 0;
        if (ZMODE) zi = 512 + z[m];
#pragma unroll
        for (int j = 0; j < 8; j++) {
            int n = col0 + ((j < 4) ? (tx * 4 + j) : (64 + tx * 4 + j - 4));
            float v = acc[i][j] + bias[n];
            if (bias2) v += bias2[n];
            if (ZMODE) v += B[(size_t)n * ldb + zi];
            if (ACT) v = v > 0.f ? v : 0.01f * v;
            C[(size_t)m * N + n] = v;
        }
    }
}

// ----------------------------------------------------------------------------
// LSTM step v2: f32x2 packed across batch pairs.
// 128 blocks (4 j each), 256 threads = 64 bp x 4 jj.
// ----------------------------------------------------------------------------
__device__ __forceinline__ float sigm(float x) { return 1.f / (1.f + expf(-x)); }

__global__ __launch_bounds__(256) void lstm_step2(
    const float* __restrict__ xg, const float* __restrict__ whh,
    const int* __restrict__ done,
    const float* __restrict__ h_in, float* __restrict__ h_out,
    float* __restrict__ c_st, float* __restrict__ feat, int t) {
    __shared__ ull s_hm[64 * 34];   // (b0,b1) masked pairs, padded stride
    __shared__ ull s_wd[16 * 34];   // duplicated weight pairs
    __shared__ float s_m[128];
    int tid = threadIdx.x;
    int bn = blockIdx.x;
    int j0 = bn * 4;

    if (tid < 128) s_m[tid] = 1.0f - (float)done[t * 128 + tid];

    int jj = tid & 3;
    int bp = tid >> 2;      // 0..63
    int b0 = bp * 2;

    ull acc[4];
#pragma unroll
    for (int g = 0; g < 4; g++) {
        float x0 = xg[(size_t)(t * 128 + b0) * 2048 + g * 512 + j0 + jj];
        float x1 = xg[(size_t)(t * 128 + b0 + 1) * 2048 + g * 512 + j0 + jj];
        acc[g] = fpack(x0, x1);
    }
    __syncthreads();

    int sb = tid & 63;      // staging bp
    int sq = tid >> 6;      // staging k-quarter
    int wr = tid >> 3;      // weight row (tid<128): g*4+jj
    int wc = (tid & 7) * 4;
    int wg = wr >> 2, wjj = wr & 3;
    const float* wrow = whh + (size_t)(wg * 512 + j0 + wjj) * 512;

    for (int k0 = 0; k0 < 512; k0 += 32) {
        {   // stage masked h pairs
            float m0 = s_m[2 * sb], m1 = s_m[2 * sb + 1];
            const float* hp0 = h_in + (size_t)(2 * sb) * 512 + k0 + sq * 8;
            const float* hp1 = hp0 + 512;
            float4 a = *(const float4*)hp0;
            float4 bq = *(const float4*)(hp0 + 4);
            float4 c = *(const float4*)hp1;
            float4 d = *(const float4*)(hp1 + 4);
            ull* dst = s_hm + sb * 34 + sq * 8;
            dst[0] = fpack(a.x * m0, c.x * m1);
            dst[1] = fpack(a.y * m0, c.y * m1);
            dst[2] = fpack(a.z * m0, c.z * m1);
            dst[3] = fpack(a.w * m0, c.w * m1);
            dst[4] = fpack(bq.x * m0, d.x * m1);
            dst[5] = fpack(bq.y * m0, d.y * m1);
            dst[6] = fpack(bq.z * m0, d.z * m1);
            dst[7] = fpack(bq.w * m0, d.w * m1);
        }
        if (tid < 128) {  // stage duplicated weights
            float4 wv = *(const float4*)(wrow + k0 + wc);
            ull* dw = s_wd + wr * 34 + wc;
            dw[0] = fpack(wv.x, wv.x);
            dw[1] = fpack(wv.y, wv.y);
            dw[2] = fpack(wv.z, wv.z);
            dw[3] = fpack(wv.w, wv.w);
        }
        __syncthreads();
#pragma unroll
        for (int kq = 0; kq < 8; kq++) {
            ulonglong2 h01 = *(const ulonglong2*)(s_hm + bp * 34 + kq * 4);
            ulonglong2 h23 = *(const ulonglong2*)(s_hm + bp * 34 + kq * 4 + 2);
#pragma unroll
            for (int g = 0; g < 4; g++) {
                const ull* wptr = s_wd + (g * 4 + jj) * 34 + kq * 4;
                ulonglong2 w01 = *(const ulonglong2*)wptr;
                ulonglong2 w23 = *(const ulonglong2*)(wptr + 2);
                ffma2(acc[g], h01.x, w01.x);
                ffma2(acc[g], h01.y, w01.y);
                ffma2(acc[g], h23.x, w23.x);
                ffma2(acc[g], h23.y, w23.y);
            }
        }
        __syncthreads();
    }

    int j = j0 + jj;
#pragma unroll
    for (int bb = 0; bb < 2; bb++) {
        int b = b0 + bb;
        float gi, gf, gg, go, t0, t1;
        funpack(acc[0], t0, t1); gi = bb ? t1 : t0;
        funpack(acc[1], t0, t1); gf = bb ? t1 : t0;
        funpack(acc[2], t0, t1); gg = bb ? t1 : t0;
        funpack(acc[3], t0, t1); go = bb ? t1 : t0;
        float mm = s_m[b];
        float cn = sigm(gf) * (c_st[b * 512 + j] * mm) + sigm(gi) * tanhf(gg);
        float hn = sigm(go) * tanhf(cn);
        c_st[b * 512 + j] = cn;
        h_out[b * 512 + j] = hn;
        feat[(size_t)(t * 128 + b) * 512 + j] = hn;
    }
}

// ----------------------------------------------------------------------------
// Head: warp per row; actor/critic GEMV + log_softmax/entropy/prob pack.
// ----------------------------------------------------------------------------
__global__ __launch_bounds__(256) void head_kernel(
    const float* __restrict__ lf, const float* __restrict__ aw,
    const float* __restrict__ ab, const float* __restrict__ cw,
    const float* __restrict__ cb, const int* __restrict__ action,
    float* __restrict__ out) {
    int warp = (blockIdx.x * blockDim.x + threadIdx.x) >> 5;
    int lane = threadIdx.x & 31;
    if (warp >= TBTOT) return;
    float4 f = *(const float4*)(lf + (size_t)warp * FE + lane * 4);
    float r[8];
#pragma unroll
    for (int a = 0; a < 7; a++) {
        float4 w = *(const float4*)(aw + a * FE + lane * 4);
        r[a] = f.x * w.x + f.y * w.y + f.z * w.z + f.w * w.w;
    }
    {
        float4 w = *(const float4*)(cw + lane * 4);
        r[7] = f.x * w.x + f.y * w.y + f.z * w.z + f.w * w.w;
    }
#pragma unroll
    for (int a = 0; a < 8; a++)
#pragma unroll
        for (int s = 16; s > 0; s >>= 1)
            r[a] += __shfl_xor_sync(0xffffffffu, r[a], s);

    if (lane == 0) {
        float lg[7];
        float mx = -1e30f;
#pragma unroll
        for (int a = 0; a < 7; a++) {
            lg[a] = r[a] + ab[a];
            mx = fmaxf(mx, lg[a]);
        }
        float se = 0.f;
        float e[7];
#pragma unroll
        for (int a = 0; a < 7; a++) {
            e[a] = expf(lg[a] - mx);
            se += e[a];
        }
        float lse = mx + logf(se);
        float inv = 1.f / se;
        float ent = 0.f;
        float* o = out + (size_t)warp * 10;
#pragma unroll
        for (int a = 0; a < 7; a++) {
            float p = e[a] * inv;
            float lp = lg[a] - lse;
            ent -= p * lp;
            o[3 + a] = p;
        }
        int act = action[warp];
        o[0] = lg[act] - lse;
        o[1] = ent;
        o[2] = r[7] + cb[0];
    }
}

// ----------------------------------------------------------------------------
// Launch
// ----------------------------------------------------------------------------
extern "C" void kernel_launch(void* const* d_in, const int* in_sizes, int n_in,
                              void* d_out, int out_size) {
    const float* x    = (const float*)d_in[0];
    const int* done   = (const int*)d_in[1];
    const int* z      = (const int*)d_in[2];
    const int* action = (const int*)d_in[3];
    const float* h0   = (const float*)d_in[4];
    const float* c0   = (const float*)d_in[5];
    const float* c1w = (const float*)d_in[6];  const float* c1b = (const float*)d_in[7];
    const float* c2w = (const float*)d_in[8];  const float* c2b = (const float*)d_in[9];
    const float* c3w = (const float*)d_in[10]; const float* c3b = (const float*)d_in[11];
    const float* fc1w = (const float*)d_in[12]; const float* fc1b = (const float*)d_in[13];
    const float* fc2w = (const float*)d_in[14]; const float* fc2b = (const float*)d_in[15];
    const float* wih = (const float*)d_in[16]; const float* whh = (const float*)d_in[17];
    const float* bih = (const float*)d_in[18]; const float* bhh = (const float*)d_in[19];
    const float* lfw = (const float*)d_in[20]; const float* lfb = (const float*)d_in[21];
    const float* aw = (const float*)d_in[22];  const float* ab = (const float*)d_in[23];
    const float* cw = (const float*)d_in[24];  const float* cb = (const float*)d_in[25];
    float* out = (float*)d_out;

    float *pconv, *ph1, *ph2, *pxg, *pfeat, *plf, *phA, *phB, *pc;
    __nv_bfloat16 *pw1h, *pw1l, *pw2h, *pw2l, *pwih_h, *pwih_l;
    cudaGetSymbolAddress((void**)&pconv, g_conv);
    cudaGetSymbolAddress((void**)&ph1, g_h1);
    cudaGetSymbolAddress((void**)&ph2, g_h2);
    cudaGetSymbolAddress((void**)&pxg, g_xg);
    cudaGetSymbolAddress((void**)&pfeat, g_feat);
    cudaGetSymbolAddress((void**)&plf, g_lf);
    cudaGetSymbolAddress((void**)&phA, g_hA);
    cudaGetSymbolAddress((void**)&phB, g_hB);
    cudaGetSymbolAddress((void**)&pc, g_c);
    cudaGetSymbolAddress((void**)&pw1h, g_wfc1_hi);
    cudaGetSymbolAddress((void**)&pw1l, g_wfc1_lo);
    cudaGetSymbolAddress((void**)&pw2h, g_wfc2_hi);
    cudaGetSymbolAddress((void**)&pw2l, g_wfc2_lo);
    cudaGetSymbolAddress((void**)&pwih_h, g_wih_hi);
    cudaGetSymbolAddress((void**)&pwih_l, g_wih_lo);

    const int SMEM_TG = 128 * 132 * 4;
    cudaFuncSetAttribute(tgemm<1>, cudaFuncAttributeMaxDynamicSharedMemorySize, SMEM_TG);
    cudaFuncSetAttribute(tgemm<0>, cudaFuncAttributeMaxDynamicSharedMemorySize, SMEM_TG);
    const int SMEM_CONV = (3216 + 3328) * 8 + 64;
    cudaFuncSetAttribute(conv3_v2, cudaFuncAttributeMaxDynamicSharedMemorySize, SMEM_CONV);

    // weight prep (split fp32 -> bf16 hi/lo)
    wprep<<<(512 * 1024 + 255) / 256, 256>>>(fc1w, pw1h, pw1l, 512 * 1024);
    wprep<<<(512 * 128 + 255) / 256, 256>>>(fc2w, pw2h, pw2l, 512 * 128);
    wprep<<<(2048 * 128 + 255) / 256, 256>>>(wih, pwih_h, pwih_l, 2048 * 128);

    // conv stack (packed f32x2)
    conv3_v2<<<TBTOT, 256, SMEM_CONV>>>(x, c1w, c1b, c2w, c2b, c3w, c3b);

    // tensor-core (HMMA) GEMMs
    tgemm<1><<<dim3(512 / 128, TBTOT / 128), 256, SMEM_TG>>>(
        pconv, pw1h, pw1l, fc1b, nullptr, ph1, TBTOT, 512, 4096);
    tgemm<1><<<dim3(512 / 128, TBTOT / 128), 256, SMEM_TG>>>(
        ph1, pw2h, pw2l, fc2b, nullptr, ph2, TBTOT, 512, 512);
    tgemm<0><<<dim3(2048 / 128, TBTOT / 128), 256, SMEM_TG>>>(
        ph2, pwih_h, pwih_l, bih, bhh, pxg, TBTOT, 2048, 512);

    // initial LSTM state
    cudaMemcpyAsync(phA, h0, (size_t)B_ENV * HID * sizeof(float),
                    cudaMemcpyDeviceToDevice, 0);
    cudaMemcpyAsync(pc, c0, (size_t)B_ENV * HID * sizeof(float),
                    cudaMemcpyDeviceToDevice, 0);

    // sequential recurrence, ping-pong h
    for (int t = 0; t < T_STEPS; t++) {
        float* hin = (t & 1) ? phB : phA;
        float* hout = (t & 1) ? phA : phB;
        lstm_step2<<<128, 256>>>(pxg, whh, done, hin, hout, pc, pfeat, t);
    }

    // lofeat: feat(512) + one-hot(z) via epilogue, ldb=520, leaky
    sgemm128<1, 1><<<dim3(FE / 128, TBTOT / 128), 256>>>(
        pfeat, lfw, lfb, nullptr, plf, TBTOT, FE, 512, 520, z);

    // heads + softmax stats
    head_kernel<<<TBTOT / 8, 256>>>(plf, aw, ab, cw, cb, action, out);
}

// round 5
// speedup vs baseline: 1.6057x; 1.6057x over previous
#include <cuda_runtime.h>
#include <cuda_bf16.h>
#include <math.h>
#include <stdint.h>

#define T_STEPS 128
#define B_ENV   128
#define HID     512
#define TBTOT   (T_STEPS * B_ENV)
#define ZD      8
#define AD      7
#define FE      128

// ----------------------------------------------------------------------------
// Scratch (device globals; no allocation allowed)
// ----------------------------------------------------------------------------
__device__ float g_conv[TBTOT * 4096];
__device__ float g_h1[TBTOT * HID];
__device__ float g_h2[TBTOT * HID];
__device__ float g_xg[TBTOT * 2048];
__device__ float g_feat[TBTOT * HID];
__device__ float g_lf[TBTOT * FE];
__device__ float g_hA[B_ENV * HID];
__device__ float g_hB[B_ENV * HID];
__device__ float g_c[B_ENV * HID];
__device__ __nv_bfloat16 g_wfc1_hi[512 * 4096];
__device__ __nv_bfloat16 g_wfc1_lo[512 * 4096];
__device__ __nv_bfloat16 g_wfc2_hi[512 * 512];
__device__ __nv_bfloat16 g_wfc2_lo[512 * 512];
__device__ __nv_bfloat16 g_wih_hi[2048 * 512];
__device__ __nv_bfloat16 g_wih_lo[2048 * 512];
// conv weights, tap-major: [tap][co*16+ci] bf16 hi/lo
__device__ __nv_bfloat16 g_cw1h[25 * 256];
__device__ __nv_bfloat16 g_cw1l[25 * 256];
__device__ __nv_bfloat16 g_cw2h[9 * 256];
__device__ __nv_bfloat16 g_cw2l[9 * 256];
__device__ __nv_bfloat16 g_cw3h[9 * 256];
__device__ __nv_bfloat16 g_cw3l[9 * 256];

// ============================================================================
// Helpers
// ============================================================================
__device__ __forceinline__ uint32_t smem_to_u32(const void* smem_ptr) {
    uint32_t addr;
    asm("{ .reg .u64 tmp; cvta.to.shared.u64 tmp, %1; cvt.u32.u64 %0, tmp; }"
        : "=r"(addr) : "l"(smem_ptr));
    return addr;
}

__device__ __forceinline__ void ldsm4(uint32_t addr, uint32_t* r) {
    asm volatile("ldmatrix.sync.aligned.m8n8.x4.shared.b16 {%0,%1,%2,%3}, [%4];"
        : "=r"(r[0]), "=r"(r[1]), "=r"(r[2]), "=r"(r[3]) : "r"(addr));
}

__device__ __forceinline__ void mma16816(float* d, const uint32_t* a,
                                         const uint32_t* b) {
    asm volatile(
        "mma.sync.aligned.m16n8k16.row.col.f32.bf16.bf16.f32 "
        "{%0,%1,%2,%3}, {%4,%5,%6,%7}, {%8,%9}, {%0,%1,%2,%3};"
        : "+f"(d[0]), "+f"(d[1]), "+f"(d[2]), "+f"(d[3])
        : "r"(a[0]), "r"(a[1]), "r"(a[2]), "r"(a[3]), "r"(b[0]), "r"(b[1]));
}

__device__ __forceinline__ void split2(float x, float y, uint32_t& hi, uint32_t& lo) {
    __nv_bfloat16 hx = __float2bfloat16(x), hy = __float2bfloat16(y);
    __nv_bfloat162 h2; h2.x = hx; h2.y = hy;
    hi = reinterpret_cast<uint32_t&>(h2);
    float lx = x - __bfloat162float(hx);
    float ly = y - __bfloat162float(hy);
    __nv_bfloat162 l2 = __floats2bfloat162_rn(lx, ly);
    lo = reinterpret_cast<uint32_t&>(l2);
}

// ----------------------------------------------------------------------------
// Weight prep: fp32 [N,K] row-major -> bf16 hi/lo row-major (for tgemm)
// ----------------------------------------------------------------------------
__global__ void wprep(const float* __restrict__ w, __nv_bfloat16* __restrict__ hi,
                      __nv_bfloat16* __restrict__ lo, int total4) {
    int idx = blockIdx.x * blockDim.x + threadIdx.x;
    if (idx >= total4) return;
    float4 a = *(const float4*)(w + (size_t)idx * 4);
    uint32_t h0, h1, l0, l1;
    split2(a.x, a.y, h0, l0);
    split2(a.z, a.w, h1, l1);
    *(uint2*)(hi + (size_t)idx * 4) = make_uint2(h0, h1);
    *(uint2*)(lo + (size_t)idx * 4) = make_uint2(l0, l1);
}

// conv weights [co][ci][taps] fp32 -> [tap][co*16+ci] bf16 hi/lo
__global__ void wcprep(const float* __restrict__ w, __nv_bfloat16* __restrict__ hi,
                       __nv_bfloat16* __restrict__ lo, int taps) {
    int idx = blockIdx.x * blockDim.x + threadIdx.x;
    if (idx >= taps * 256) return;
    int r = idx & 255;
    int t = idx >> 8;
    float v = w[r * taps + t];
    __nv_bfloat16 hv = __float2bfloat16(v);
    float lv = v - __bfloat162float(hv);
    hi[t * 256 + r] = hv;
    lo[t * 256 + r] = __float2bfloat16(lv);
}

// ----------------------------------------------------------------------------
// HMMA GEMM (unchanged, proven): 3-term bf16 split, fp32 accum
// ----------------------------------------------------------------------------
#define SMSTR 80

template <int ACT>
__global__ __launch_bounds__(256) void tgemm(
    const float* __restrict__ A, const __nv_bfloat16* __restrict__ Whi,
    const __nv_bfloat16* __restrict__ Wlo,
    const float* __restrict__ bias, const float* __restrict__ bias2,
    float* __restrict__ C, int M, int N, int K) {
    extern __shared__ uint8_t sm[];
    const uint32_t oAh = 0, oAl = 10240, oBh = 20480, oBl = 30720;
    uint32_t sb = smem_to_u32(sm);
    int tid = threadIdx.x;
    int lane = tid & 31;
    int wid = tid >> 5;
    int wm = wid & 3, wn = wid >> 2;
    int m0 = blockIdx.y * 128, n0 = blockIdx.x * 128;
    const float* Ag = A + (size_t)m0 * K;

    float acc[2][8][4];
#pragma unroll
    for (int i = 0; i < 2; i++)
#pragma unroll
        for (int j = 0; j < 8; j++)
#pragma unroll
            for (int q = 0; q < 4; q++) acc[i][j][q] = 0.f;

    int nslab = K / 32;
    float4 aR[4];
    uint4 bRh[2], bRl[2];

    auto load_slab = [&](int s) {
#pragma unroll
        for (int i = 0; i < 4; i++) {
            int row = (tid >> 3) + 32 * i;
            aR[i] = *(const float4*)(Ag + (size_t)row * K + s * 32 + (tid & 7) * 4);
        }
#pragma unroll
        for (int i = 0; i < 2; i++) {
            int row = (tid >> 2) + 64 * i;
            size_t boff = ((size_t)(n0 + row) * K + s * 32);
            bRh[i] = *(const uint4*)((const uint8_t*)(Whi + boff) + (tid & 3) * 16);
            bRl[i] = *(const uint4*)((const uint8_t*)(Wlo + boff) + (tid & 3) * 16);
        }
    };
    auto store_slab = [&]() {
#pragma unroll
        for (int i = 0; i < 4; i++) {
            int row = (tid >> 3) + 32 * i;
            int col8 = (tid & 7) * 8;
            uint32_t h0, h1, l0, l1;
            split2(aR[i].x, aR[i].y, h0, l0);
            split2(aR[i].z, aR[i].w, h1, l1);
            *(uint2*)(sm + oAh + row * SMSTR + col8) = make_uint2(h0, h1);
            *(uint2*)(sm + oAl + row * SMSTR + col8) = make_uint2(l0, l1);
        }
#pragma unroll
        for (int i = 0; i < 2; i++) {
            int row = (tid >> 2) + 64 * i;
            int c16 = (tid & 3) * 16;
            *(uint4*)(sm + oBh + row * SMSTR + c16) = bRh[i];
            *(uint4*)(sm + oBl + row * SMSTR + c16) = bRl[i];
        }
    };

    load_slab(0);
    store_slab();
    __syncthreads();

    int g = lane >> 3;
    int arow_off = (lane & 7) + (g & 1) * 8;
    int akb_off = (g >> 1) * 16;
    int brow_off = (lane & 7) + (g >> 1) * 8;
    int bkb_off = (g & 1) * 16;

    for (int s = 0; s < nslab; s++) {
        bool more = (s + 1 < nslab);
        if (more) load_slab(s + 1);

#pragma unroll
        for (int kk2 = 0; kk2 < 2; kk2++) {
            int kb = kk2 * 32;
            uint32_t ah[2][4], al[2][4], bh[4][4], bl[4][4];
#pragma unroll
            for (int mi = 0; mi < 2; mi++) {
                uint32_t r = (uint32_t)((wm * 32 + mi * 16 + arow_off) * SMSTR +
                                        kb + akb_off);
                ldsm4(sb + oAh + r, ah[mi]);
                ldsm4(sb + oAl + r, al[mi]);
            }
#pragma unroll
            for (int pi = 0; pi < 4; pi++) {
                uint32_t r = (uint32_t)((wn * 64 + pi * 16 + brow_off) * SMSTR +
                                        kb + bkb_off);
                ldsm4(sb + oBh + r, bh[pi]);
                ldsm4(sb + oBl + r, bl[pi]);
            }
#pragma unroll
            for (int mi = 0; mi < 2; mi++)
#pragma unroll
                for (int pi = 0; pi < 4; pi++)
#pragma unroll
                    for (int half = 0; half < 2; half++) {
                        float* d = acc[mi][pi * 2 + half];
                        mma16816(d, ah[mi], &bh[pi][half * 2]);
                        mma16816(d, ah[mi], &bl[pi][half * 2]);
                        mma16816(d, al[mi], &bh[pi][half * 2]);
                    }
        }
        __syncthreads();
        if (more) {
            store_slab();
            __syncthreads();
        }
    }

    float* ct = (float*)sm;
#pragma unroll
    for (int mi = 0; mi < 2; mi++) {
        int r0 = wm * 32 + mi * 16 + (lane >> 2);
#pragma unroll
        for (int ni = 0; ni < 8; ni++) {
            int c = wn * 64 + ni * 8 + (lane & 3) * 2;
            float b0 = bias[n0 + c], b1 = bias[n0 + c + 1];
            if (bias2) { b0 += bias2[n0 + c]; b1 += bias2[n0 + c + 1]; }
            float v0 = acc[mi][ni][0] + b0;
            float v1 = acc[mi][ni][1] + b1;
            float v2 = acc[mi][ni][2] + b0;
            float v3 = acc[mi][ni][3] + b1;
            if (ACT) {
                v0 = v0 > 0.f ? v0 : 0.01f * v0;
                v1 = v1 > 0.f ? v1 : 0.01f * v1;
                v2 = v2 > 0.f ? v2 : 0.01f * v2;
                v3 = v3 > 0.f ? v3 : 0.01f * v3;
            }
            ct[r0 * 132 + c] = v0;
            ct[r0 * 132 + c + 1] = v1;
            ct[(r0 + 8) * 132 + c] = v2;
            ct[(r0 + 8) * 132 + c + 1] = v3;
        }
    }
    __syncthreads();
    {
        int r8 = tid >> 5;
        int c4 = (tid & 31) * 4;
#pragma unroll
        for (int p = 0; p < 16; p++) {
            int r = p * 8 + r8;
            float4 v = *(const float4*)(ct + r * 132 + c4);
            *(float4*)(C + (size_t)(m0 + r) * N + n0 + c4) = v;
        }
    }
}

// ----------------------------------------------------------------------------
// HMMA conv: per-image tap-GEMM. Block = 1 image, 8 warps (2 h-rows each).
// smem image: padded 20x20 positions x 16 ci bf16, 48B position stride
// (16B-aligned, conflict-free ldsm rows), zero halo. Weights: per-tap
// [co=16][ci=16] tiles, 32B rows. 3-term bf16 hi/lo split, fp32 mma accum.
// ----------------------------------------------------------------------------
#define PSTR 48                       // bytes per position
#define IMG_BYTES (400 * PSTR)        // 19200
#define CW_OFF   (2 * IMG_BYTES)      // 38400
#define CW_HALF  12800                // 25 taps * 512B max

template <int KS, int P, int LAST>
__device__ __forceinline__ void conv_hmma_layer(
    uint8_t* csm, uint32_t sbase, const __nv_bfloat16* wsrc_h,
    const __nv_bfloat16* wsrc_l, const float* __restrict__ bias,
    float* gout, int tid, int lane, int wid) {
    const int taps = KS * KS;
    // load tap weights (coalesced uint4)
    {
        const uint4* sh = (const uint4*)wsrc_h;
        const uint4* sl = (const uint4*)wsrc_l;
        uint4* dh = (uint4*)(csm + CW_OFF);
        uint4* dl = (uint4*)(csm + CW_OFF + CW_HALF);
        for (int i = tid; i < taps * 32; i += 256) {
            dh[i] = sh[i];
            dl[i] = sl[i];
        }
    }
    __syncthreads();

    float acc[2][2][4];
#pragma unroll
    for (int a = 0; a < 2; a++)
#pragma unroll
        for (int b = 0; b < 2; b++)
#pragma unroll
            for (int q = 0; q < 4; q++) acc[a][b][q] = 0.f;

    int g = lane >> 3;
    int h0 = wid * 2;
    // A: rows = w (pixels of one h-row), k = ci
    uint32_t aoff[2];
#pragma unroll
    for (int mi = 0; mi < 2; mi++)
        aoff[mi] = (uint32_t)(((h0 + mi + 2) * 20 + 2 + (lane & 7) + (g & 1) * 8) * PSTR +
                              (g >> 1) * 16);
    // B: rows = co, 32B rows
    uint32_t boff = (uint32_t)(((lane & 7) + (g >> 1) * 8) * 32 + (g & 1) * 16);
    uint32_t wb_h = sbase + CW_OFF;
    uint32_t wb_l = sbase + CW_OFF + CW_HALF;

#pragma unroll
    for (int kh = 0; kh < KS; kh++) {
#pragma unroll
        for (int kw = 0; kw < KS; kw++) {
            int t = kh * KS + kw;
            int shift = ((kh - P) * 20 + (kw - P)) * PSTR;
            uint32_t bh4[4], bl4[4];
            ldsm4(wb_h + t * 512 + boff, bh4);
            ldsm4(wb_l + t * 512 + boff, bl4);
#pragma unroll
            for (int mi = 0; mi < 2; mi++) {
                uint32_t ah[4], al[4];
                ldsm4(sbase + aoff[mi] + shift, ah);
                ldsm4(sbase + IMG_BYTES + aoff[mi] + shift, al);
#pragma unroll
                for (int nh = 0; nh < 2; nh++) {
                    mma16816(acc[mi][nh], ah, &bh4[nh * 2]);
                    mma16816(acc[mi][nh], ah, &bl4[nh * 2]);
                    mma16816(acc[mi][nh], al, &bh4[nh * 2]);
                }
            }
        }
    }
    __syncthreads();   // all reads of image done before overwrite

    // epilogue: bias + leaky; write back split (or final fp32 to gmem)
#pragma unroll
    for (int mi = 0; mi < 2; mi++) {
        int h = h0 + mi;
#pragma unroll
        for (int nh = 0; nh < 2; nh++) {
            int co = nh * 8 + (lane & 3) * 2;
            float b0 = bias[co], b1 = bias[co + 1];
#pragma unroll
            for (int rr = 0; rr < 2; rr++) {
                int w = (lane >> 2) + rr * 8;
                float v0 = acc[mi][nh][rr * 2 + 0] + b0;
                float v1 = acc[mi][nh][rr * 2 + 1] + b1;
                v0 = v0 > 0.f ? v0 : 0.01f * v0;
                v1 = v1 > 0.f ? v1 : 0.01f * v1;
                if (LAST) {
                    gout[co * 256 + h * 16 + w] = v0;
                    gout[(co + 1) * 256 + h * 16 + w] = v1;
                } else {
                    uint32_t hp, lp;
                    split2(v0, v1, hp, lp);
                    int pb = ((h + 2) * 20 + (w + 2)) * PSTR + co * 2;
                    *(uint32_t*)(csm + pb) = hp;
                    *(uint32_t*)(csm + IMG_BYTES + pb) = lp;
                }
            }
        }
    }
    __syncthreads();
}

__global__ __launch_bounds__(256) void conv3_mma(
    const float* __restrict__ x,
    const float* __restrict__ b1, const float* __restrict__ b2,
    const float* __restrict__ b3) {
    extern __shared__ uint8_t csm[];
    uint32_t sbase = smem_to_u32(csm);
    int tid = threadIdx.x;
    int lane = tid & 31;
    int wid = tid >> 5;
    int img = blockIdx.x;
    const float* xi = x + (size_t)img * 4096;

    // zero both padded images (halo correctness)
    for (int i = tid; i < 2 * IMG_BYTES / 4; i += 256)
        ((uint32_t*)csm)[i] = 0;
    __syncthreads();
    // fill interior: x[ci][h][w] -> img[(h,w)][ci], split hi/lo
    for (int i = tid; i < 4096; i += 256) {
        int ci = i >> 8, p = i & 255;
        int h = p >> 4, w = p & 15;
        float v = xi[i];
        __nv_bfloat16 hv = __float2bfloat16(v);
        float lv = v - __bfloat162float(hv);
        int pb = ((h + 2) * 20 + (w + 2)) * PSTR + ci * 2;
        *(__nv_bfloat16*)(csm + pb) = hv;
        *(__nv_bfloat16*)(csm + IMG_BYTES + pb) = __float2bfloat16(lv);
    }
    __syncthreads();

    float* gout = g_conv + (size_t)img * 4096;
    conv_hmma_layer<5, 2, 0>(csm, sbase, g_cw1h, g_cw1l, b1, gout, tid, lane, wid);
    conv_hmma_layer<3, 1, 0>(csm, sbase, g_cw2h, g_cw2l, b2, gout, tid, lane, wid);
    conv_hmma_layer<3, 1, 1>(csm, sbase, g_cw3h, g_cw3l, b3, gout, tid, lane, wid);
}

// ----------------------------------------------------------------------------
// Scalar SGEMM kept for lofeat (with z one-hot epilogue)
// ----------------------------------------------------------------------------
template <int ACT, int ZMODE>
__global__ __launch_bounds__(256, 2) void sgemm128(
    const float* __restrict__ A, const float* __restrict__ B,
    const float* __restrict__ bias, const float* __restrict__ bias2,
    float* __restrict__ C, int M, int N, int K, int ldb,
    const int* __restrict__ z) {
    __shared__ float As[8 * 132];
    __shared__ float Bs[8 * 132];
    int tid = threadIdx.x;
    int tx = tid & 15, ty = tid >> 4;
    int row0 = blockIdx.y * 128;
    int col0 = blockIdx.x * 128;
    const float* Ag = A + (size_t)row0 * K;
    const float* Bg = B + (size_t)col0 * ldb;
    int lr = tid >> 1;
    int lc = (tid & 1) * 4;

    float acc[8][8];
#pragma unroll
    for (int i = 0; i < 8; i++)
#pragma unroll
        for (int j = 0; j < 8; j++) acc[i][j] = 0.f;

    for (int k0 = 0; k0 < K; k0 += 8) {
        float4 a4 = *(const float4*)(Ag + (size_t)lr * K + k0 + lc);
        float4 b4 = *(const float4*)(Bg + (size_t)lr * ldb + k0 + lc);
        As[(lc + 0) * 132 + lr] = a4.x;
        As[(lc + 1) * 132 + lr] = a4.y;
        As[(lc + 2) * 132 + lr] = a4.z;
        As[(lc + 3) * 132 + lr] = a4.w;
        Bs[(lc + 0) * 132 + lr] = b4.x;
        Bs[(lc + 1) * 132 + lr] = b4.y;
        Bs[(lc + 2) * 132 + lr] = b4.z;
        Bs[(lc + 3) * 132 + lr] = b4.w;
        __syncthreads();
#pragma unroll
        for (int k = 0; k < 8; k++) {
            float4 a0 = *(const float4*)(As + k * 132 + ty * 4);
            float4 a1 = *(const float4*)(As + k * 132 + 64 + ty * 4);
            float4 b0 = *(const float4*)(Bs + k * 132 + tx * 4);
            float4 b1 = *(const float4*)(Bs + k * 132 + 64 + tx * 4);
            float av[8] = {a0.x, a0.y, a0.z, a0.w, a1.x, a1.y, a1.z, a1.w};
            float bv[8] = {b0.x, b0.y, b0.z, b0.w, b1.x, b1.y, b1.z, b1.w};
#pragma unroll
            for (int i = 0; i < 8; i++)
#pragma unroll
                for (int j = 0; j < 8; j++)
                    acc[i][j] = fmaf(av[i], bv[j], acc[i][j]);
        }
        __syncthreads();
    }

#pragma unroll
    for (int i = 0; i < 8; i++) {
        int m = row0 + ((i < 4) ? (ty * 4 + i) : (64 + ty * 4 + i - 4));
        int zi = 0;
        if (ZMODE) zi = 512 + z[m];
#pragma unroll
        for (int j = 0; j < 8; j++) {
            int n = col0 + ((j < 4) ? (tx * 4 + j) : (64 + tx * 4 + j - 4));
            float v = acc[i][j] + bias[n];
            if (bias2) v += bias2[n];
            if (ZMODE) v += B[(size_t)n * ldb + zi];
            if (ACT) v = v > 0.f ? v : 0.01f * v;
            C[(size_t)m * N + n] = v;
        }
    }
}

// ----------------------------------------------------------------------------
// LSTM step (R3 version — known good): 256 threads, 2 batches x 4 gates/thread
// ----------------------------------------------------------------------------
__device__ __forceinline__ float sigm(float x) { return 1.f / (1.f + expf(-x)); }

__global__ __launch_bounds__(256) void lstm_step(
    const float* __restrict__ xg, const float* __restrict__ whh,
    const int* __restrict__ done,
    const float* __restrict__ h_in, float* __restrict__ h_out,
    float* __restrict__ c_st, float* __restrict__ feat, int t) {
    __shared__ float s_hm[128 * 36];
    __shared__ float s_w[16 * 36];
    __shared__ float s_m[128];
    int tid = threadIdx.x;
    int bn = blockIdx.x;
    int j0 = bn * 4;

    if (tid < 128) s_m[tid] = 1.0f - (float)done[t * 128 + tid];

    int jj = tid & 3;
    int b0 = (tid >> 2) * 2;

    float acc[2][4];
#pragma unroll
    for (int bb = 0; bb < 2; bb++)
#pragma unroll
        for (int g = 0; g < 4; g++)
            acc[bb][g] = xg[(size_t)(t * 128 + b0 + bb) * 2048 + g * 512 + j0 + jj];
    __syncthreads();

    int wr = tid >> 3;
    int wc = (tid & 7) * 4;
    int wg = wr >> 2, wjj = wr & 3;
    const float* wrow = whh + (size_t)(wg * 512 + j0 + wjj) * 512;

    for (int k0 = 0; k0 < 512; k0 += 32) {
#pragma unroll
        for (int i = 0; i < 4; i++) {
            int idx = tid + 256 * i;
            int b = idx >> 3;
            int c4 = (idx & 7) * 4;
            float4 hv = *(const float4*)(h_in + b * 512 + k0 + c4);
            float mm = s_m[b];
            hv.x *= mm; hv.y *= mm; hv.z *= mm; hv.w *= mm;
            *(float4*)(s_hm + b * 36 + c4) = hv;
        }
        if (tid < 128)
            *(float4*)(s_w + wr * 36 + wc) = *(const float4*)(wrow + k0 + wc);
        __syncthreads();
#pragma unroll
        for (int kq = 0; kq < 8; kq++) {
            float4 wv[4];
#pragma unroll
            for (int g = 0; g < 4; g++)
                wv[g] = *(const float4*)(s_w + (g * 4 + jj) * 36 + kq * 4);
#pragma unroll
            for (int bb = 0; bb < 2; bb++) {
                float4 av = *(const float4*)(s_hm + (b0 + bb) * 36 + kq * 4);
#pragma unroll
                for (int g = 0; g < 4; g++) {
                    acc[bb][g] = fmaf(av.x, wv[g].x, acc[bb][g]);
                    acc[bb][g] = fmaf(av.y, wv[g].y, acc[bb][g]);
                    acc[bb][g] = fmaf(av.z, wv[g].z, acc[bb][g]);
                    acc[bb][g] = fmaf(av.w, wv[g].w, acc[bb][g]);
                }
            }
        }
        __syncthreads();
    }

    int j = j0 + jj;
#pragma unroll
    for (int bb = 0; bb < 2; bb++) {
        int b = b0 + bb;
        float mm = s_m[b];
        float ig = sigm(acc[bb][0]);
        float fg = sigm(acc[bb][1]);
        float gg = tanhf(acc[bb][2]);
        float og = sigm(acc[bb][3]);
        float cn = fg * (c_st[b * 512 + j] * mm) + ig * gg;
        float hn = og * tanhf(cn);
        c_st[b * 512 + j] = cn;
        h_out[b * 512 + j] = hn;
        feat[(size_t)(t * 128 + b) * 512 + j] = hn;
    }
}

// ----------------------------------------------------------------------------
// Head: warp per row; actor/critic GEMV + log_softmax/entropy/prob pack.
// ----------------------------------------------------------------------------
__global__ __launch_bounds__(256) void head_kernel(
    const float* __restrict__ lf, const float* __restrict__ aw,
    const float* __restrict__ ab, const float* __restrict__ cw,
    const float* __restrict__ cb, const int* __restrict__ action,
    float* __restrict__ out) {
    int warp = (blockIdx.x * blockDim.x + threadIdx.x) >> 5;
    int lane = threadIdx.x & 31;
    if (warp >= TBTOT) return;
    float4 f = *(const float4*)(lf + (size_t)warp * FE + lane * 4);
    float r[8];
#pragma unroll
    for (int a = 0; a < 7; a++) {
        float4 w = *(const float4*)(aw + a * FE + lane * 4);
        r[a] = f.x * w.x + f.y * w.y + f.z * w.z + f.w * w.w;
    }
    {
        float4 w = *(const float4*)(cw + lane * 4);
        r[7] = f.x * w.x + f.y * w.y + f.z * w.z + f.w * w.w;
    }
#pragma unroll
    for (int a = 0; a < 8; a++)
#pragma unroll
        for (int s = 16; s > 0; s >>= 1)
            r[a] += __shfl_xor_sync(0xffffffffu, r[a], s);

    if (lane == 0) {
        float lg[7];
        float mx = -1e30f;
#pragma unroll
        for (int a = 0; a < 7; a++) {
            lg[a] = r[a] + ab[a];
            mx = fmaxf(mx, lg[a]);
        }
        float se = 0.f;
        float e[7];
#pragma unroll
        for (int a = 0; a < 7; a++) {
            e[a] = expf(lg[a] - mx);
            se += e[a];
        }
        float lse = mx + logf(se);
        float inv = 1.f / se;
        float ent = 0.f;
        float* o = out + (size_t)warp * 10;
#pragma unroll
        for (int a = 0; a < 7; a++) {
            float p = e[a] * inv;
            float lp = lg[a] - lse;
            ent -= p * lp;
            o[3 + a] = p;
        }
        int act = action[warp];
        o[0] = lg[act] - lse;
        o[1] = ent;
        o[2] = r[7] + cb[0];
    }
}

// ----------------------------------------------------------------------------
// Launch
// ----------------------------------------------------------------------------
extern "C" void kernel_launch(void* const* d_in, const int* in_sizes, int n_in,
                              void* d_out, int out_size) {
    const float* x    = (const float*)d_in[0];
    const int* done   = (const int*)d_in[1];
    const int* z      = (const int*)d_in[2];
    const int* action = (const int*)d_in[3];
    const float* h0   = (const float*)d_in[4];
    const float* c0   = (const float*)d_in[5];
    const float* c1w = (const float*)d_in[6];  const float* c1b = (const float*)d_in[7];
    const float* c2w = (const float*)d_in[8];  const float* c2b = (const float*)d_in[9];
    const float* c3w = (const float*)d_in[10]; const float* c3b = (const float*)d_in[11];
    const float* fc1w = (const float*)d_in[12]; const float* fc1b = (const float*)d_in[13];
    const float* fc2w = (const float*)d_in[14]; const float* fc2b = (const float*)d_in[15];
    const float* wih = (const float*)d_in[16]; const float* whh = (const float*)d_in[17];
    const float* bih = (const float*)d_in[18]; const float* bhh = (const float*)d_in[19];
    const float* lfw = (const float*)d_in[20]; const float* lfb = (const float*)d_in[21];
    const float* aw = (const float*)d_in[22];  const float* ab = (const float*)d_in[23];
    const float* cw = (const float*)d_in[24];  const float* cb = (const float*)d_in[25];
    float* out = (float*)d_out;

    float *pconv, *ph1, *ph2, *pxg, *pfeat, *plf, *phA, *phB, *pc;
    __nv_bfloat16 *pw1h, *pw1l, *pw2h, *pw2l, *pwih_h, *pwih_l;
    __nv_bfloat16 *pc1h, *pc1l, *pc2h, *pc2l, *pc3h, *pc3l;
    cudaGetSymbolAddress((void**)&pconv, g_conv);
    cudaGetSymbolAddress((void**)&ph1, g_h1);
    cudaGetSymbolAddress((void**)&ph2, g_h2);
    cudaGetSymbolAddress((void**)&pxg, g_xg);
    cudaGetSymbolAddress((void**)&pfeat, g_feat);
    cudaGetSymbolAddress((void**)&plf, g_lf);
    cudaGetSymbolAddress((void**)&phA, g_hA);
    cudaGetSymbolAddress((void**)&phB, g_hB);
    cudaGetSymbolAddress((void**)&pc, g_c);
    cudaGetSymbolAddress((void**)&pw1h, g_wfc1_hi);
    cudaGetSymbolAddress((void**)&pw1l, g_wfc1_lo);
    cudaGetSymbolAddress((void**)&pw2h, g_wfc2_hi);
    cudaGetSymbolAddress((void**)&pw2l, g_wfc2_lo);
    cudaGetSymbolAddress((void**)&pwih_h, g_wih_hi);
    cudaGetSymbolAddress((void**)&pwih_l, g_wih_lo);
    cudaGetSymbolAddress((void**)&pc1h, g_cw1h);
    cudaGetSymbolAddress((void**)&pc1l, g_cw1l);
    cudaGetSymbolAddress((void**)&pc2h, g_cw2h);
    cudaGetSymbolAddress((void**)&pc2l, g_cw2l);
    cudaGetSymbolAddress((void**)&pc3h, g_cw3h);
    cudaGetSymbolAddress((void**)&pc3l, g_cw3l);

    const int SMEM_TG = 128 * 132 * 4;
    cudaFuncSetAttribute(tgemm<1>, cudaFuncAttributeMaxDynamicSharedMemorySize, SMEM_TG);
    cudaFuncSetAttribute(tgemm<0>, cudaFuncAttributeMaxDynamicSharedMemorySize, SMEM_TG);
    const int SMEM_CONV = 2 * IMG_BYTES + 2 * CW_HALF;   // 64000
    cudaFuncSetAttribute(conv3_mma, cudaFuncAttributeMaxDynamicSharedMemorySize, SMEM_CONV);

    // weight prep
    wprep<<<(512 * 1024 + 255) / 256, 256>>>(fc1w, pw1h, pw1l, 512 * 1024);
    wprep<<<(512 * 128 + 255) / 256, 256>>>(fc2w, pw2h, pw2l, 512 * 128);
    wprep<<<(2048 * 128 + 255) / 256, 256>>>(wih, pwih_h, pwih_l, 2048 * 128);
    wcprep<<<25, 256>>>(c1w, pc1h, pc1l, 25);
    wcprep<<<9, 256>>>(c2w, pc2h, pc2l, 9);
    wcprep<<<9, 256>>>(c3w, pc3h, pc3l, 9);

    // conv stack (HMMA tap-GEMM)
    conv3_mma<<<TBTOT, 256, SMEM_CONV>>>(x, c1b, c2b, c3b);

    // tensor-core (HMMA) GEMMs
    tgemm<1><<<dim3(512 / 128, TBTOT / 128), 256, SMEM_TG>>>(
        pconv, pw1h, pw1l, fc1b, nullptr, ph1, TBTOT, 512, 4096);
    tgemm<1><<<dim3(512 / 128, TBTOT / 128), 256, SMEM_TG>>>(
        ph1, pw2h, pw2l, fc2b, nullptr, ph2, TBTOT, 512, 512);
    tgemm<0><<<dim3(2048 / 128, TBTOT / 128), 256, SMEM_TG>>>(
        ph2, pwih_h, pwih_l, bih, bhh, pxg, TBTOT, 2048, 512);

    // initial LSTM state
    cudaMemcpyAsync(phA, h0, (size_t)B_ENV * HID * sizeof(float),
                    cudaMemcpyDeviceToDevice, 0);
    cudaMemcpyAsync(pc, c0, (size_t)B_ENV * HID * sizeof(float),
                    cudaMemcpyDeviceToDevice, 0);

    // sequential recurrence, ping-pong h
    for (int t = 0; t < T_STEPS; t++) {
        float* hin = (t & 1) ? phB : phA;
        float* hout = (t & 1) ? phA : phB;
        lstm_step<<<128, 256>>>(pxg, whh, done, hin, hout, pc, pfeat, t);
    }

    // lofeat: feat(512) + one-hot(z) via epilogue, ldb=520, leaky
    sgemm128<1, 1><<<dim3(FE / 128, TBTOT / 128), 256>>>(
        pfeat, lfw, lfb, nullptr, plf, TBTOT, FE, 512, 520, z);

    // heads + softmax stats
    head_kernel<<<TBTOT / 8, 256>>>(plf, aw, ab, cw, cb, action, out);
}